// round 11
// baseline (speedup 1.0000x reference)
#include <cuda_runtime.h>
#include <math.h>

#define BATCH 8
#define LL    128
#define NSPAN 1928
#define KSEL  10
#define WPB   16
#define BSK   (BATCH*NSPAN*KSEL)
#define NWORD 61   // ceil(1928/32)

// ---------------- device scratch (static: allowed) ----------------
__device__ unsigned g_lr  [NSPAN];            // l | r<<8
__device__ uint4    g_cand[BATCH * NSPAN];    // {ptk, w0, w1, w2} (w as bits)
__device__ float    g_G   [BATCH * LL * LL];  // exp(-dist)
__device__ unsigned g_A   [BATCH * LL * 4];   // (dist<=2) bitmask rows
// ptk byte0 = top1 (0xFF = excluded/invalid/capped), bytes1-3 = merged tokens (0xFF pad)

__device__ __forceinline__ int span_base(int l) {
    return (l <= 113) ? (l << 4) : (NSPAN - (((128 - l) * (129 - l)) >> 1));
}
__device__ __forceinline__ void span_lr(int s, int* l, int* r) {
    int ll_;
    if (s < 1808) { ll_ = s >> 4; }
    else {
        ll_ = 113;
        for (int c = 113; c < 127; c++) if (span_base(c + 1) <= s) ll_ = c + 1;
    }
    *l = ll_; *r = ll_ + (s - span_base(ll_));
}

// ---------------- input classification (int32 vs int64 vs float) ----------------
__device__ __forceinline__ int classify(const unsigned* p) {
    bool allSmall = true, oddZero = true, anyNZ = false;
    for (int i = 0; i < 64; i++) {
        unsigned v = p[i];
        if (v >= 128u) allSmall = false;
        if ((i & 1) && v != 0u) oddZero = false;
        if (!(i & 1) && v != 0u) anyNZ = true;
    }
    if (!allSmall) return 0;
    return (oddZero && anyNZ) ? 2 : 1;
}

// ---------------- K0: spans + G=exp(-dist) + A bitmask, fused ----------------
#define EXP_BLOCKS ((BATCH * LL * LL) / 256)   // 512
__global__ void k_pre(const float* __restrict__ dist) {
    int bx = blockIdx.x;
    if (bx < EXP_BLOCKS) {
        int i = bx * 256 + threadIdx.x;
        float d = dist[i];
        g_G[i] = expf(-d);
        unsigned m = __ballot_sync(0xffffffffu, d <= 2.0f);
        if ((threadIdx.x & 31) == 0) g_A[i >> 5] = m;
    } else {
        int s = (bx - EXP_BLOCKS) * 256 + threadIdx.x;
        if (s < NSPAN) {
            int l, r; span_lr(s, &l, &r);
            g_lr[s] = (unsigned)l | ((unsigned)r << 8);
        }
    }
}

__device__ __forceinline__ long long read_idx(const void* p, int wide, int off) {
    return wide ? ((const long long*)p)[off] : (long long)((const int*)p)[off];
}

// ---------------- K1: token compaction -> packed uint4 ----------------
__global__ void k_tok(const void* __restrict__ inA, const void* __restrict__ inB) {
    __shared__ int s_swap, s_wide;
    if (threadIdx.x == 0) {
        int cA = classify((const unsigned*)inA), cB = classify((const unsigned*)inB);
        if      (cA > 0) { s_swap = 0; s_wide = (cA == 2); }
        else if (cB > 0) { s_swap = 1; s_wide = (cB == 2); }
        else             { s_swap = 0; s_wide = 0; }
    }
    __syncthreads();
    int gid = blockIdx.x * blockDim.x + threadIdx.x;
    if (gid >= BATCH * NSPAN) return;
    const void*  pIdx = s_swap ? inB : inA;
    const float* hw   = (const float*)(s_swap ? inA : inB);
    int wide = s_wide;

    int b = gid / NSPAN, s = gid - b * NSPAN;
    unsigned lr = g_lr[s];
    int off = ((b * LL + (int)(lr & 0xFF)) * LL + (int)((lr >> 8) & 0xFF)) * 4;

    int ik[3]; float wk[3]; long long raw0 = -1;
    #pragma unroll
    for (int k = 0; k < 3; k++) {
        long long raw = read_idx(pIdx, wide, off + k);
        if (k == 0) raw0 = raw;
        bool v = (raw >= 0);
        ik[k] = v ? (int)raw : (1000 + k);
        wk[k] = v ? hw[off + k] : 0.0f;
    }
    unsigned top1 = (raw0 >= 0) ? (unsigned)min((int)raw0, LL - 1) : 0xFFu;

    bool a1 = true, a2 = true;
    if (ik[1] == ik[0]) { wk[0] = __fadd_rn(wk[0], wk[1]); a1 = false; }
    if (ik[2] == ik[0]) { wk[0] = __fadd_rn(wk[0], wk[2]); a2 = false; }
    else if (a1 && ik[2] == ik[1]) { wk[1] = __fadd_rn(wk[1], wk[2]); a2 = false; }

    int mi[3] = {255, 255, 255}; float mw[3] = {0.f, 0.f, 0.f}; int cnt = 0;
    if (ik[0] < LL)       { mi[cnt] = ik[0]; mw[cnt] = wk[0]; cnt++; }
    if (a1 && ik[1] < LL) { mi[cnt] = ik[1]; mw[cnt] = wk[1]; cnt++; }
    if (a2 && ik[2] < LL) { mi[cnt] = ik[2]; mw[cnt] = wk[2]; cnt++; }

    if (cnt >= 2 && mi[0] > mi[1]) { int t = mi[0]; mi[0] = mi[1]; mi[1] = t;
                                     float f = mw[0]; mw[0] = mw[1]; mw[1] = f; }
    if (cnt == 3) {
        if (mi[1] > mi[2]) { int t = mi[1]; mi[1] = mi[2]; mi[2] = t;
                             float f = mw[1]; mw[1] = mw[2]; mw[2] = f; }
        if (mi[0] > mi[1]) { int t = mi[0]; mi[0] = mi[1]; mi[1] = t;
                             float f = mw[0]; mw[0] = mw[1]; mw[1] = f; }
    }
    unsigned ptk = top1 | ((unsigned)mi[0] << 8) | ((unsigned)mi[1] << 16)
                 | ((unsigned)mi[2] << 24);
    g_cand[gid] = make_uint4(ptk, __float_as_uint(mw[0]),
                             __float_as_uint(mw[1]), __float_as_uint(mw[2]));
}

// ---------------- K2: CAP folded into top1 byte ----------------
__global__ void k_cap() {
    __shared__ unsigned sp[NSPAN];
    int b = blockIdx.x, l = threadIdx.x;
    for (int i = l; i < NSPAN; i += 128) sp[i] = g_cand[b * NSPAN + i].x;
    __syncthreads();
    int cnt = 0;
    for (int t = 0; t < NSPAN; t++) {
        if ((sp[t] & 0xFFu) == (unsigned)l) {
            cnt++;
            if (cnt > 128) sp[t] |= 0xFFu;
        }
    }
    __syncthreads();
    for (int i = l; i < NSPAN; i += 128) g_cand[b * NSPAN + i].x = sp[i];
}

// ---------------- K3 (captured slot): main gate + masked top-10 ----------------
__global__ void __launch_bounds__(WPB * 32, 1)
k_main(float* __restrict__ out) {
    __shared__ uint4    sCand[NSPAN];             // 30848 B
    __shared__ float    sApw[WPB][LL];            //  8192 B
    __shared__ unsigned sGeo[WPB][64];            //  4096 B

    int b = blockIdx.y;
    int tid = threadIdx.x, lane = tid & 31, warp = tid >> 5;
    int base = b * NSPAN;

    for (int i = tid; i < NSPAN; i += WPB * 32)
        sCand[i] = g_cand[base + i];
    __syncthreads();

    int s = blockIdx.x * WPB + warp;
    if (s >= NSPAN) return;

    uint4 cs = sCand[s];
    unsigned ptk_s = cs.x;
    int t0 = (ptk_s >>  8) & 0xFF;
    int t1 = (ptk_s >> 16) & 0xFF;
    int t2 = (ptk_s >> 24) & 0xFF;
    float w0 = __uint_as_float(cs.y);
    float w1 = __uint_as_float(cs.z);
    float w2 = __uint_as_float(cs.w);
    const float*    Gb = g_G + b * LL * LL;
    const unsigned* Ab = g_A + b * LL * 4;

    // U bitmask (4 ballot words in registers, all lanes) + A_pw row
    unsigned bal[4];
    #pragma unroll
    for (int q = 0; q < 4; q++) {
        int m = q * 32 + lane;
        bool bit = false;
        if (t0 < LL) bit |= (t0 == m) || ((Ab[t0 * 4 + q] >> lane) & 1u);
        if (t1 < LL) bit |= (t1 == m) || ((Ab[t1 * 4 + q] >> lane) & 1u);
        if (t2 < LL) bit |= (t2 == m) || ((Ab[t2 * 4 + q] >> lane) & 1u);
        bal[q] = __ballot_sync(0xffffffffu, bit);
        float a = __fmaf_rn(w0, Gb[(t0 & 0x7F) * LL + m], 0.0f);
        a = __fmaf_rn(w1, Gb[(t1 & 0x7F) * LL + m], a);
        a = __fmaf_rn(w2, Gb[(t2 & 0x7F) * LL + m], a);
        sApw[warp][m] = a;
    }
    // distribute U words: lane j holds word j (j<4), lanes 4-31 hold 0
    unsigned uw = (lane == 0) ? bal[0] : (lane == 1) ? bal[1]
                : (lane == 2) ? bal[2] : (lane == 3) ? bal[3] : 0u;

    // per-warp geom bitmask over candidate ids
    sGeo[warp][lane] = 0u; sGeo[warp][32 + lane] = 0u;
    __syncwarp();
    if (lane == 0) {
        unsigned lr_s = g_lr[s];
        int ls = lr_s & 0xFF, rs = (lr_s >> 8) & 0xFF;
        const int dl[8] = {-1,-1,-1, 0, 0, 1, 1, 1};
        const int dr[8] = {-1, 0, 1,-1, 1,-1, 0, 1};
        #pragma unroll
        for (int j = 0; j < 8; j++) {
            int nl = ls + dl[j], nr = rs + dr[j];
            if (nl >= 0 && nr >= nl && nr < LL && (nr - nl) <= 15) {
                int id = span_base(nl) + (nr - nl);
                sGeo[warp][id >> 5] |= (1u << (id & 31));
            }
        }
    }
    __syncwarp();

    float vv[KSEL]; int vi[KSEL];
    #pragma unroll
    for (int j = 0; j < KSEL; j++) { vv[j] = -INFINITY; vi[j] = s; }
    const float* apw = sApw[warp];

    for (int k = 0; k < NWORD; k++) {
        int t = k * 32 + lane;
        unsigned gw = sGeo[warp][k];                        // broadcast LDS
        uint4 cd = (t < NSPAN) ? sCand[t]
                               : make_uint4(0xFFu, 0u, 0u, 0u);
        unsigned byte = cd.x & 0xFFu;
        unsigned w_ = __shfl_sync(0xffffffffu, uw, byte >> 5);
        unsigned ub = (w_ >> (byte & 31)) & 1u;
        bool pass = ((ub | ((gw >> lane) & 1u)) && t != s);
        if (!pass) continue;

        float g = __fmaf_rn(__uint_as_float(cd.y), apw[(cd.x >>  8) & 0x7F], 0.0f);
        g = __fmaf_rn(__uint_as_float(cd.z), apw[(cd.x >> 16) & 0x7F], g);
        g = __fmaf_rn(__uint_as_float(cd.w), apw[(cd.x >> 24) & 0x7F], g);

        if (g > vv[KSEL - 1]) {
            vv[KSEL - 1] = g; vi[KSEL - 1] = t;
            #pragma unroll
            for (int j = KSEL - 2; j >= 0; j--) {
                if (vv[j + 1] > vv[j]) {
                    float tv = vv[j]; vv[j] = vv[j + 1]; vv[j + 1] = tv;
                    int   ti = vi[j]; vi[j] = vi[j + 1]; vi[j + 1] = ti;
                }
            }
        }
    }

    // butterfly merge: snapshot partner's FULL list before mutating
    #pragma unroll
    for (int off = 16; off >= 1; off >>= 1) {
        float pv[KSEL]; int pi[KSEL];
        #pragma unroll
        for (int j = 0; j < KSEL; j++) {
            pv[j] = __shfl_xor_sync(0xffffffffu, vv[j], off);
            pi[j] = __shfl_xor_sync(0xffffffffu, vi[j], off);
        }
        #pragma unroll
        for (int j = 0; j < KSEL; j++) {
            float p = pv[j]; int q = pi[j];
            bool better = (p > vv[KSEL - 1]) ||
                          (p == vv[KSEL - 1] && p != -INFINITY && q < vi[KSEL - 1]);
            if (better) {
                vv[KSEL - 1] = p; vi[KSEL - 1] = q;
                #pragma unroll
                for (int k2 = KSEL - 2; k2 >= 0; k2--) {
                    bool sw = (vv[k2 + 1] > vv[k2]) ||
                              (vv[k2 + 1] == vv[k2] && vi[k2 + 1] < vi[k2]);
                    if (sw) {
                        float tv = vv[k2]; vv[k2] = vv[k2 + 1]; vv[k2 + 1] = tv;
                        int   ti = vi[k2]; vi[k2] = vi[k2 + 1]; vi[k2 + 1] = ti;
                    }
                }
            }
        }
    }

    if (lane == 0) {
        int ob = (base + s) * KSEL;
        #pragma unroll
        for (int j = 0; j < KSEL; j++) out[ob + j] = (float)vi[j];
    }
}

// ---------------- K4: mask-tail fill only ----------------
__global__ void k_tail(float* __restrict__ out, int out_size) {
    int i = BSK + blockIdx.x * blockDim.x + threadIdx.x;
    if (i < out_size) out[i] = 1.0f;
}

// ---------------- launch ----------------
extern "C" void kernel_launch(void* const* d_in, const int* in_sizes, int n_in,
                              void* d_out, int out_size) {
    const void* pA = d_in[0];
    const void* pB = d_in[1];
    const float* dist = (const float*)d_in[2];
    if (in_sizes[0] == BATCH * LL * LL)      { dist = (const float*)d_in[0]; pA = d_in[1]; pB = d_in[2]; }
    else if (in_sizes[1] == BATCH * LL * LL) { dist = (const float*)d_in[1]; pA = d_in[0]; pB = d_in[2]; }
    float* out = (float*)d_out;

    k_pre<<<EXP_BLOCKS + (NSPAN + 255) / 256, 256>>>(dist);          // idx 0
    k_tok<<<(BATCH * NSPAN + 255) / 256, 256>>>(pA, pB);             // idx 1
    k_cap<<<BATCH, 128>>>();                                          // idx 2
    dim3 grid((NSPAN + WPB - 1) / WPB, BATCH);
    k_main<<<grid, WPB * 32>>>(out);                                  // idx 3 (captured)
    int tail = out_size - BSK;
    if (tail > 0) k_tail<<<(tail + 255) / 256, 256>>>(out, out_size); // idx 4
}

// round 13
// speedup vs baseline: 1.1338x; 1.1338x over previous
#include <cuda_runtime.h>
#include <math.h>

#define BATCH 8
#define LL    128
#define NSPAN 1928
#define KSEL  10
#define WPB   16
#define BSK   (BATCH*NSPAN*KSEL)
#define NWORD 61   // ceil(1928/32)

// ---------------- device scratch (static: allowed) ----------------
__device__ unsigned g_lr  [NSPAN];            // l | r<<8
__device__ uint4    g_cand[BATCH * NSPAN];    // {ptk, w0, w1, w2} (w as bits)
__device__ float    g_G   [BATCH * LL * LL];  // exp(-dist)
__device__ unsigned g_A   [BATCH * LL * 4];   // (dist<=2) bitmask rows
// ptk byte0 = top1 (0xFF = excluded/invalid/capped), bytes1-3 = merged tokens (0xFF pad)

__device__ __forceinline__ int span_base(int l) {
    return (l <= 113) ? (l << 4) : (NSPAN - (((128 - l) * (129 - l)) >> 1));
}
__device__ __forceinline__ void span_lr(int s, int* l, int* r) {
    int ll_;
    if (s < 1808) { ll_ = s >> 4; }
    else {
        ll_ = 113;
        for (int c = 113; c < 127; c++) if (span_base(c + 1) <= s) ll_ = c + 1;
    }
    *l = ll_; *r = ll_ + (s - span_base(ll_));
}

// ---------------- input classification (int32 vs int64 vs float) ----------------
__device__ __forceinline__ int classify(const unsigned* p) {
    bool allSmall = true, oddZero = true, anyNZ = false;
    for (int i = 0; i < 64; i++) {
        unsigned v = p[i];
        if (v >= 128u) allSmall = false;
        if ((i & 1) && v != 0u) oddZero = false;
        if (!(i & 1) && v != 0u) anyNZ = true;
    }
    if (!allSmall) return 0;
    return (oddZero && anyNZ) ? 2 : 1;
}

// ---------------- K0: spans + G=exp(-dist) + A bitmask, fused ----------------
#define EXP_BLOCKS ((BATCH * LL * LL) / 256)   // 512
__global__ void k_pre(const float* __restrict__ dist) {
    int bx = blockIdx.x;
    if (bx < EXP_BLOCKS) {
        int i = bx * 256 + threadIdx.x;
        float d = dist[i];
        g_G[i] = expf(-d);
        unsigned m = __ballot_sync(0xffffffffu, d <= 2.0f);
        if ((threadIdx.x & 31) == 0) g_A[i >> 5] = m;
    } else {
        int s = (bx - EXP_BLOCKS) * 256 + threadIdx.x;
        if (s < NSPAN) {
            int l, r; span_lr(s, &l, &r);
            g_lr[s] = (unsigned)l | ((unsigned)r << 8);
        }
    }
}

__device__ __forceinline__ long long read_idx(const void* p, int wide, int off) {
    return wide ? ((const long long*)p)[off] : (long long)((const int*)p)[off];
}

// ---------------- K1: token compaction -> packed uint4 ----------------
__global__ void k_tok(const void* __restrict__ inA, const void* __restrict__ inB) {
    __shared__ int s_swap, s_wide;
    if (threadIdx.x == 0) {
        int cA = classify((const unsigned*)inA), cB = classify((const unsigned*)inB);
        if      (cA > 0) { s_swap = 0; s_wide = (cA == 2); }
        else if (cB > 0) { s_swap = 1; s_wide = (cB == 2); }
        else             { s_swap = 0; s_wide = 0; }
    }
    __syncthreads();
    int gid = blockIdx.x * blockDim.x + threadIdx.x;
    if (gid >= BATCH * NSPAN) return;
    const void*  pIdx = s_swap ? inB : inA;
    const float* hw   = (const float*)(s_swap ? inA : inB);
    int wide = s_wide;

    int b = gid / NSPAN, s = gid - b * NSPAN;
    unsigned lr = g_lr[s];
    int off = ((b * LL + (int)(lr & 0xFF)) * LL + (int)((lr >> 8) & 0xFF)) * 4;

    int ik[3]; float wk[3]; long long raw0 = -1;
    #pragma unroll
    for (int k = 0; k < 3; k++) {
        long long raw = read_idx(pIdx, wide, off + k);
        if (k == 0) raw0 = raw;
        bool v = (raw >= 0);
        ik[k] = v ? (int)raw : (1000 + k);
        wk[k] = v ? hw[off + k] : 0.0f;
    }
    unsigned top1 = (raw0 >= 0) ? (unsigned)min((int)raw0, LL - 1) : 0xFFu;

    bool a1 = true, a2 = true;
    if (ik[1] == ik[0]) { wk[0] = __fadd_rn(wk[0], wk[1]); a1 = false; }
    if (ik[2] == ik[0]) { wk[0] = __fadd_rn(wk[0], wk[2]); a2 = false; }
    else if (a1 && ik[2] == ik[1]) { wk[1] = __fadd_rn(wk[1], wk[2]); a2 = false; }

    int mi[3] = {255, 255, 255}; float mw[3] = {0.f, 0.f, 0.f}; int cnt = 0;
    if (ik[0] < LL)       { mi[cnt] = ik[0]; mw[cnt] = wk[0]; cnt++; }
    if (a1 && ik[1] < LL) { mi[cnt] = ik[1]; mw[cnt] = wk[1]; cnt++; }
    if (a2 && ik[2] < LL) { mi[cnt] = ik[2]; mw[cnt] = wk[2]; cnt++; }

    if (cnt >= 2 && mi[0] > mi[1]) { int t = mi[0]; mi[0] = mi[1]; mi[1] = t;
                                     float f = mw[0]; mw[0] = mw[1]; mw[1] = f; }
    if (cnt == 3) {
        if (mi[1] > mi[2]) { int t = mi[1]; mi[1] = mi[2]; mi[2] = t;
                             float f = mw[1]; mw[1] = mw[2]; mw[2] = f; }
        if (mi[0] > mi[1]) { int t = mi[0]; mi[0] = mi[1]; mi[1] = t;
                             float f = mw[0]; mw[0] = mw[1]; mw[1] = f; }
    }
    unsigned ptk = top1 | ((unsigned)mi[0] << 8) | ((unsigned)mi[1] << 16)
                 | ((unsigned)mi[2] << 24);
    g_cand[gid] = make_uint4(ptk, __float_as_uint(mw[0]),
                             __float_as_uint(mw[1]), __float_as_uint(mw[2]));
}

// ---------------- K2: CAP folded into top1 byte ----------------
__global__ void k_cap() {
    __shared__ unsigned sp[NSPAN];
    int b = blockIdx.x, l = threadIdx.x;
    for (int i = l; i < NSPAN; i += 128) sp[i] = g_cand[b * NSPAN + i].x;
    __syncthreads();
    int cnt = 0;
    for (int t = 0; t < NSPAN; t++) {
        if ((sp[t] & 0xFFu) == (unsigned)l) {
            cnt++;
            if (cnt > 128) sp[t] |= 0xFFu;
        }
    }
    __syncthreads();
    for (int i = l; i < NSPAN; i += 128) g_cand[b * NSPAN + i].x = sp[i];
}

// ---------------- K3 (captured slot): main gate + masked top-10 ----------------
// u64 key = (f32_bits(gate) << 11) | (2047 - t): gate >= 0 so float bits are
// order-monotonic; ties prefer smaller t; key 0 == empty slot (emit s).
__global__ void __launch_bounds__(WPB * 32, 1)
k_main(float* __restrict__ out) {
    __shared__ uint4    sCand[NSPAN];             // 30848 B
    __shared__ float    sApw[WPB][LL];            //  8192 B
    __shared__ unsigned sU[WPB][8];               //   512 B
    __shared__ unsigned sGeo[WPB][64];            //  4096 B

    int b = blockIdx.y;
    int tid = threadIdx.x, lane = tid & 31, warp = tid >> 5;
    int base = b * NSPAN;

    for (int i = tid; i < NSPAN; i += WPB * 32)
        sCand[i] = g_cand[base + i];
    __syncthreads();

    int s = blockIdx.x * WPB + warp;
    if (s >= NSPAN) return;

    uint4 cs = sCand[s];
    int t0 = (cs.x >>  8) & 0xFF;
    int t1 = (cs.x >> 16) & 0xFF;
    int t2 = (cs.x >> 24) & 0xFF;
    float w0 = __uint_as_float(cs.y);
    float w1 = __uint_as_float(cs.z);
    float w2 = __uint_as_float(cs.w);
    const float*    Gb = g_G + b * LL * LL;
    const unsigned* Ab = g_A + b * LL * 4;

    // U bitmask + A_pw row (identical FFMA chain to the passing R10/R11)
    #pragma unroll
    for (int q = 0; q < 4; q++) {
        int m = q * 32 + lane;
        bool bit = false;
        if (t0 < LL) bit |= (t0 == m) || ((Ab[t0 * 4 + q] >> lane) & 1u);
        if (t1 < LL) bit |= (t1 == m) || ((Ab[t1 * 4 + q] >> lane) & 1u);
        if (t2 < LL) bit |= (t2 == m) || ((Ab[t2 * 4 + q] >> lane) & 1u);
        unsigned bal = __ballot_sync(0xffffffffu, bit);
        if (lane == 0) { sU[warp][q] = bal; sU[warp][q + 4] = 0u; }
        float a = __fmaf_rn(w0, Gb[(t0 & 0x7F) * LL + m], 0.0f);
        a = __fmaf_rn(w1, Gb[(t1 & 0x7F) * LL + m], a);
        a = __fmaf_rn(w2, Gb[(t2 & 0x7F) * LL + m], a);
        sApw[warp][m] = a;
    }
    // per-warp geom bitmask over candidate ids
    sGeo[warp][lane] = 0u; sGeo[warp][32 + lane] = 0u;
    __syncwarp();
    if (lane == 0) {
        unsigned lr_s = g_lr[s];
        int ls = lr_s & 0xFF, rs = (lr_s >> 8) & 0xFF;
        const int dl[8] = {-1,-1,-1, 0, 0, 1, 1, 1};
        const int dr[8] = {-1, 0, 1,-1, 1,-1, 0, 1};
        #pragma unroll
        for (int j = 0; j < 8; j++) {
            int nl = ls + dl[j], nr = rs + dr[j];
            if (nl >= 0 && nr >= nl && nr < LL && (nr - nl) <= 15) {
                int id = span_base(nl) + (nr - nl);
                sGeo[warp][id >> 5] |= (1u << (id & 31));
            }
        }
    }
    __syncwarp();

    unsigned long long kv[KSEL];
    #pragma unroll
    for (int j = 0; j < KSEL; j++) kv[j] = 0ull;
    const float* apw = sApw[warp];

    #pragma unroll 2
    for (int k = 0; k < NWORD; k++) {
        int t = k * 32 + lane;
        int tc = (t < NSPAN) ? t : (NSPAN - 1);
        uint4 cd = sCand[tc];
        unsigned gw = sGeo[warp][k];                 // broadcast, conflict-free
        unsigned byte = cd.x & 0xFFu;
        unsigned w_ = sU[warp][byte >> 5];           // 8 words, 8 banks: multicast
        bool pass = ((((w_ >> (byte & 31)) | (gw >> lane)) & 1u) != 0u)
                    && (t != s) && (t < NSPAN);

        float g = __fmaf_rn(__uint_as_float(cd.y), apw[(cd.x >>  8) & 0x7F], 0.0f);
        g = __fmaf_rn(__uint_as_float(cd.z), apw[(cd.x >> 16) & 0x7F], g);
        g = __fmaf_rn(__uint_as_float(cd.w), apw[(cd.x >> 24) & 0x7F], g);

        unsigned long long key = pass
            ? ((((unsigned long long)__float_as_uint(g)) << 11)
               | (unsigned long long)(2047 - t))
            : 0ull;

        if (key > kv[KSEL - 1]) {
            kv[KSEL - 1] = key;
            #pragma unroll
            for (int j = KSEL - 2; j >= 0; j--) {
                if (kv[j + 1] > kv[j]) {
                    unsigned long long tk = kv[j]; kv[j] = kv[j + 1]; kv[j + 1] = tk;
                }
            }
        }
    }

    // butterfly merge: snapshot partner's sorted list, early-break insert
    #pragma unroll
    for (int off = 16; off >= 1; off >>= 1) {
        unsigned long long pk[KSEL];
        #pragma unroll
        for (int j = 0; j < KSEL; j++)
            pk[j] = __shfl_xor_sync(0xffffffffu, kv[j], off);
        #pragma unroll
        for (int j = 0; j < KSEL; j++) {
            if (pk[j] > kv[KSEL - 1]) {
                kv[KSEL - 1] = pk[j];
                #pragma unroll
                for (int k2 = KSEL - 2; k2 >= 0; k2--) {
                    if (kv[k2 + 1] > kv[k2]) {
                        unsigned long long tk = kv[k2];
                        kv[k2] = kv[k2 + 1]; kv[k2 + 1] = tk;
                    }
                }
            } else break;   // pk sorted desc: nothing later can qualify
        }
    }

    if (lane == 0) {
        int ob = (base + s) * KSEL;
        #pragma unroll
        for (int j = 0; j < KSEL; j++) {
            unsigned long long key = kv[j];
            int t = key ? (2047 - (int)(key & 2047ull)) : s;
            out[ob + j] = (float)t;
        }
    }
}

// ---------------- K4: mask-tail fill only ----------------
__global__ void k_tail(float* __restrict__ out, int out_size) {
    int i = BSK + blockIdx.x * blockDim.x + threadIdx.x;
    if (i < out_size) out[i] = 1.0f;
}

// ---------------- launch ----------------
extern "C" void kernel_launch(void* const* d_in, const int* in_sizes, int n_in,
                              void* d_out, int out_size) {
    const void* pA = d_in[0];
    const void* pB = d_in[1];
    const float* dist = (const float*)d_in[2];
    if (in_sizes[0] == BATCH * LL * LL)      { dist = (const float*)d_in[0]; pA = d_in[1]; pB = d_in[2]; }
    else if (in_sizes[1] == BATCH * LL * LL) { dist = (const float*)d_in[1]; pA = d_in[0]; pB = d_in[2]; }
    float* out = (float*)d_out;

    k_pre<<<EXP_BLOCKS + (NSPAN + 255) / 256, 256>>>(dist);          // idx 0
    k_tok<<<(BATCH * NSPAN + 255) / 256, 256>>>(pA, pB);             // idx 1
    k_cap<<<BATCH, 128>>>();                                          // idx 2
    dim3 grid((NSPAN + WPB - 1) / WPB, BATCH);
    k_main<<<grid, WPB * 32>>>(out);                                  // idx 3 (captured)
    int tail = out_size - BSK;
    if (tail > 0) k_tail<<<(tail + 255) / 256, 256>>>(out, out_size); // idx 4
}

// round 15
// speedup vs baseline: 1.1341x; 1.0003x over previous
#include <cuda_runtime.h>
#include <math.h>

#define BATCH 8
#define LL    128
#define NSPAN 1928
#define KSEL  10
#define WPB   16
#define BSK   (BATCH*NSPAN*KSEL)
#define NWORD 61   // ceil(1928/32)

// ---------------- device scratch (static: allowed) ----------------
__device__ unsigned g_lr  [NSPAN];            // l | r<<8
__device__ uint4    g_cand[BATCH * NSPAN];    // {ptk, w0, w1, w2} (w as bits)
__device__ float    g_G   [BATCH * LL * LL];  // exp(-dist)
__device__ unsigned g_A   [BATCH * LL * 4];   // (dist<=2) bitmask rows
// ptk byte0 = top1 (0xFF = excluded/invalid/capped), bytes1-3 = merged tokens (0xFF pad)

__device__ __forceinline__ int span_base(int l) {
    return (l <= 113) ? (l << 4) : (NSPAN - (((128 - l) * (129 - l)) >> 1));
}
__device__ __forceinline__ void span_lr(int s, int* l, int* r) {
    int ll_;
    if (s < 1808) { ll_ = s >> 4; }
    else {
        ll_ = 113;
        for (int c = 113; c < 127; c++) if (span_base(c + 1) <= s) ll_ = c + 1;
    }
    *l = ll_; *r = ll_ + (s - span_base(ll_));
}

// ---------------- input classification (int32 vs int64 vs float) ----------------
__device__ __forceinline__ int classify(const unsigned* p) {
    bool allSmall = true, oddZero = true, anyNZ = false;
    for (int i = 0; i < 64; i++) {
        unsigned v = p[i];
        if (v >= 128u) allSmall = false;
        if ((i & 1) && v != 0u) oddZero = false;
        if (!(i & 1) && v != 0u) anyNZ = true;
    }
    if (!allSmall) return 0;
    return (oddZero && anyNZ) ? 2 : 1;
}

// ---------------- K0: spans + G=exp(-dist) + A bitmask, fused ----------------
#define EXP_BLOCKS ((BATCH * LL * LL) / 256)   // 512
__global__ void k_pre(const float* __restrict__ dist) {
    int bx = blockIdx.x;
    if (bx < EXP_BLOCKS) {
        int i = bx * 256 + threadIdx.x;
        float d = dist[i];
        g_G[i] = expf(-d);
        unsigned m = __ballot_sync(0xffffffffu, d <= 2.0f);
        if ((threadIdx.x & 31) == 0) g_A[i >> 5] = m;
    } else {
        int s = (bx - EXP_BLOCKS) * 256 + threadIdx.x;
        if (s < NSPAN) {
            int l, r; span_lr(s, &l, &r);
            g_lr[s] = (unsigned)l | ((unsigned)r << 8);
        }
    }
}

__device__ __forceinline__ long long read_idx(const void* p, int wide, int off) {
    return wide ? ((const long long*)p)[off] : (long long)((const int*)p)[off];
}

// ---------------- K1: token compaction -> packed uint4 ----------------
__global__ void k_tok(const void* __restrict__ inA, const void* __restrict__ inB) {
    __shared__ int s_swap, s_wide;
    if (threadIdx.x == 0) {
        int cA = classify((const unsigned*)inA), cB = classify((const unsigned*)inB);
        if      (cA > 0) { s_swap = 0; s_wide = (cA == 2); }
        else if (cB > 0) { s_swap = 1; s_wide = (cB == 2); }
        else             { s_swap = 0; s_wide = 0; }
    }
    __syncthreads();
    int gid = blockIdx.x * blockDim.x + threadIdx.x;
    if (gid >= BATCH * NSPAN) return;
    const void*  pIdx = s_swap ? inB : inA;
    const float* hw   = (const float*)(s_swap ? inA : inB);
    int wide = s_wide;

    int b = gid / NSPAN, s = gid - b * NSPAN;
    unsigned lr = g_lr[s];
    int off = ((b * LL + (int)(lr & 0xFF)) * LL + (int)((lr >> 8) & 0xFF)) * 4;

    int ik[3]; float wk[3]; long long raw0 = -1;
    #pragma unroll
    for (int k = 0; k < 3; k++) {
        long long raw = read_idx(pIdx, wide, off + k);
        if (k == 0) raw0 = raw;
        bool v = (raw >= 0);
        ik[k] = v ? (int)raw : (1000 + k);
        wk[k] = v ? hw[off + k] : 0.0f;
    }
    unsigned top1 = (raw0 >= 0) ? (unsigned)min((int)raw0, LL - 1) : 0xFFu;

    bool a1 = true, a2 = true;
    if (ik[1] == ik[0]) { wk[0] = __fadd_rn(wk[0], wk[1]); a1 = false; }
    if (ik[2] == ik[0]) { wk[0] = __fadd_rn(wk[0], wk[2]); a2 = false; }
    else if (a1 && ik[2] == ik[1]) { wk[1] = __fadd_rn(wk[1], wk[2]); a2 = false; }

    int mi[3] = {255, 255, 255}; float mw[3] = {0.f, 0.f, 0.f}; int cnt = 0;
    if (ik[0] < LL)       { mi[cnt] = ik[0]; mw[cnt] = wk[0]; cnt++; }
    if (a1 && ik[1] < LL) { mi[cnt] = ik[1]; mw[cnt] = wk[1]; cnt++; }
    if (a2 && ik[2] < LL) { mi[cnt] = ik[2]; mw[cnt] = wk[2]; cnt++; }

    if (cnt >= 2 && mi[0] > mi[1]) { int t = mi[0]; mi[0] = mi[1]; mi[1] = t;
                                     float f = mw[0]; mw[0] = mw[1]; mw[1] = f; }
    if (cnt == 3) {
        if (mi[1] > mi[2]) { int t = mi[1]; mi[1] = mi[2]; mi[2] = t;
                             float f = mw[1]; mw[1] = mw[2]; mw[2] = f; }
        if (mi[0] > mi[1]) { int t = mi[0]; mi[0] = mi[1]; mi[1] = t;
                             float f = mw[0]; mw[0] = mw[1]; mw[1] = f; }
    }
    unsigned ptk = top1 | ((unsigned)mi[0] << 8) | ((unsigned)mi[1] << 16)
                 | ((unsigned)mi[2] << 24);
    g_cand[gid] = make_uint4(ptk, __float_as_uint(mw[0]),
                             __float_as_uint(mw[1]), __float_as_uint(mw[2]));
}

// ---------------- K2: CAP folded into top1 byte ----------------
__global__ void k_cap() {
    __shared__ unsigned sp[NSPAN];
    int b = blockIdx.x, l = threadIdx.x;
    for (int i = l; i < NSPAN; i += 128) sp[i] = g_cand[b * NSPAN + i].x;
    __syncthreads();
    int cnt = 0;
    for (int t = 0; t < NSPAN; t++) {
        if ((sp[t] & 0xFFu) == (unsigned)l) {
            cnt++;
            if (cnt > 128) sp[t] |= 0xFFu;
        }
    }
    __syncthreads();
    for (int i = l; i < NSPAN; i += 128) g_cand[b * NSPAN + i].x = sp[i];
}

// ---------------- K3 (captured slot): main gate + masked top-10 ----------------
// u64 key = (f32_bits(gate) << 11) | (2047 - t): gate >= 0 so float bits are
// order-monotonic; ties prefer smaller t; key 0 == empty slot (emit s).
__global__ void __launch_bounds__(WPB * 32, 1)
k_main(float* __restrict__ out) {
    __shared__ uint4    sCand[NSPAN];             // 30848 B
    __shared__ float    sApw[WPB][LL];            //  8192 B
    __shared__ unsigned sU[WPB][8];               //   512 B
    __shared__ unsigned sGeo[WPB][64];            //  4096 B

    int b = blockIdx.y;
    int tid = threadIdx.x, lane = tid & 31, warp = tid >> 5;
    int base = b * NSPAN;

    for (int i = tid; i < NSPAN; i += WPB * 32)
        sCand[i] = g_cand[base + i];
    __syncthreads();

    int s = blockIdx.x * WPB + warp;
    if (s >= NSPAN) return;

    uint4 cs = sCand[s];
    int t0 = (cs.x >>  8) & 0xFF;
    int t1 = (cs.x >> 16) & 0xFF;
    int t2 = (cs.x >> 24) & 0xFF;
    float w0 = __uint_as_float(cs.y);
    float w1 = __uint_as_float(cs.z);
    float w2 = __uint_as_float(cs.w);
    const float*    Gb = g_G + b * LL * LL;
    const unsigned* Ab = g_A + b * LL * 4;

    // U bitmask + A_pw row (identical FFMA chain to the passing R10/R11)
    #pragma unroll
    for (int q = 0; q < 4; q++) {
        int m = q * 32 + lane;
        bool bit = false;
        if (t0 < LL) bit |= (t0 == m) || ((Ab[t0 * 4 + q] >> lane) & 1u);
        if (t1 < LL) bit |= (t1 == m) || ((Ab[t1 * 4 + q] >> lane) & 1u);
        if (t2 < LL) bit |= (t2 == m) || ((Ab[t2 * 4 + q] >> lane) & 1u);
        unsigned bal = __ballot_sync(0xffffffffu, bit);
        if (lane == 0) { sU[warp][q] = bal; sU[warp][q + 4] = 0u; }
        float a = __fmaf_rn(w0, Gb[(t0 & 0x7F) * LL + m], 0.0f);
        a = __fmaf_rn(w1, Gb[(t1 & 0x7F) * LL + m], a);
        a = __fmaf_rn(w2, Gb[(t2 & 0x7F) * LL + m], a);
        sApw[warp][m] = a;
    }
    // per-warp geom bitmask over candidate ids
    sGeo[warp][lane] = 0u; sGeo[warp][32 + lane] = 0u;
    __syncwarp();
    if (lane == 0) {
        unsigned lr_s = g_lr[s];
        int ls = lr_s & 0xFF, rs = (lr_s >> 8) & 0xFF;
        const int dl[8] = {-1,-1,-1, 0, 0, 1, 1, 1};
        const int dr[8] = {-1, 0, 1,-1, 1,-1, 0, 1};
        #pragma unroll
        for (int j = 0; j < 8; j++) {
            int nl = ls + dl[j], nr = rs + dr[j];
            if (nl >= 0 && nr >= nl && nr < LL && (nr - nl) <= 15) {
                int id = span_base(nl) + (nr - nl);
                sGeo[warp][id >> 5] |= (1u << (id & 31));
            }
        }
    }
    __syncwarp();

    unsigned long long kv[KSEL];
    #pragma unroll
    for (int j = 0; j < KSEL; j++) kv[j] = 0ull;
    const float* apw = sApw[warp];

    #pragma unroll 2
    for (int k = 0; k < NWORD; k++) {
        int t = k * 32 + lane;
        int tc = (t < NSPAN) ? t : (NSPAN - 1);
        uint4 cd = sCand[tc];
        unsigned gw = sGeo[warp][k];                 // broadcast, conflict-free
        unsigned byte = cd.x & 0xFFu;
        unsigned w_ = sU[warp][byte >> 5];           // 8 words, 8 banks: multicast
        bool pass = ((((w_ >> (byte & 31)) | (gw >> lane)) & 1u) != 0u)
                    && (t != s) && (t < NSPAN);

        float g = __fmaf_rn(__uint_as_float(cd.y), apw[(cd.x >>  8) & 0x7F], 0.0f);
        g = __fmaf_rn(__uint_as_float(cd.z), apw[(cd.x >> 16) & 0x7F], g);
        g = __fmaf_rn(__uint_as_float(cd.w), apw[(cd.x >> 24) & 0x7F], g);

        unsigned long long key = pass
            ? ((((unsigned long long)__float_as_uint(g)) << 11)
               | (unsigned long long)(2047 - t))
            : 0ull;

        if (key > kv[KSEL - 1]) {
            kv[KSEL - 1] = key;
            #pragma unroll
            for (int j = KSEL - 2; j >= 0; j--) {
                if (kv[j + 1] > kv[j]) {
                    unsigned long long tk = kv[j]; kv[j] = kv[j + 1]; kv[j + 1] = tk;
                }
            }
        }
    }

    // butterfly merge: snapshot partner's sorted list, early-break insert
    #pragma unroll
    for (int off = 16; off >= 1; off >>= 1) {
        unsigned long long pk[KSEL];
        #pragma unroll
        for (int j = 0; j < KSEL; j++)
            pk[j] = __shfl_xor_sync(0xffffffffu, kv[j], off);
        #pragma unroll
        for (int j = 0; j < KSEL; j++) {
            if (pk[j] > kv[KSEL - 1]) {
                kv[KSEL - 1] = pk[j];
                #pragma unroll
                for (int k2 = KSEL - 2; k2 >= 0; k2--) {
                    if (kv[k2 + 1] > kv[k2]) {
                        unsigned long long tk = kv[k2];
                        kv[k2] = kv[k2 + 1]; kv[k2 + 1] = tk;
                    }
                }
            } else break;   // pk sorted desc: nothing later can qualify
        }
    }

    if (lane == 0) {
        int ob = (base + s) * KSEL;
        #pragma unroll
        for (int j = 0; j < KSEL; j++) {
            unsigned long long key = kv[j];
            int t = key ? (2047 - (int)(key & 2047ull)) : s;
            out[ob + j] = (float)t;
        }
    }
}

// ---------------- K4: mask-tail fill only ----------------
__global__ void k_tail(float* __restrict__ out, int out_size) {
    int i = BSK + blockIdx.x * blockDim.x + threadIdx.x;
    if (i < out_size) out[i] = 1.0f;
}

// ---------------- launch ----------------
extern "C" void kernel_launch(void* const* d_in, const int* in_sizes, int n_in,
                              void* d_out, int out_size) {
    const void* pA = d_in[0];
    const void* pB = d_in[1];
    const float* dist = (const float*)d_in[2];
    if (in_sizes[0] == BATCH * LL * LL)      { dist = (const float*)d_in[0]; pA = d_in[1]; pB = d_in[2]; }
    else if (in_sizes[1] == BATCH * LL * LL) { dist = (const float*)d_in[1]; pA = d_in[0]; pB = d_in[2]; }
    float* out = (float*)d_out;

    k_pre<<<EXP_BLOCKS + (NSPAN + 255) / 256, 256>>>(dist);          // idx 0
    k_tok<<<(BATCH * NSPAN + 255) / 256, 256>>>(pA, pB);             // idx 1
    k_cap<<<BATCH, 128>>>();                                          // idx 2
    dim3 grid((NSPAN + WPB - 1) / WPB, BATCH);
    k_main<<<grid, WPB * 32>>>(out);                                  // idx 3 (captured)
    int tail = out_size - BSK;
    if (tail > 0) k_tail<<<(tail + 255) / 256, 256>>>(out, out_size); // idx 4
}

// round 17
// speedup vs baseline: 1.1357x; 1.0014x over previous
#include <cuda_runtime.h>
#include <math.h>

#define BATCH 8
#define LL    128
#define NSPAN 1928
#define KSEL  10
#define WPB   16
#define BSK   (BATCH*NSPAN*KSEL)
#define NWORD 61   // ceil(1928/32)

// ---------------- device scratch (static: allowed) ----------------
__device__ unsigned g_lr  [NSPAN];            // l | r<<8
__device__ uint4    g_cand[BATCH * NSPAN];    // {ptk, w0, w1, w2} (w as bits)
__device__ float    g_G   [BATCH * LL * LL];  // exp(-dist)
__device__ unsigned g_A   [BATCH * LL * 4];   // (dist<=2) bitmask rows
// ptk byte0 = top1 (0xFF = excluded/invalid/capped), bytes1-3 = merged tokens (0xFF pad)

__device__ __forceinline__ int span_base(int l) {
    return (l <= 113) ? (l << 4) : (NSPAN - (((128 - l) * (129 - l)) >> 1));
}
__device__ __forceinline__ void span_lr(int s, int* l, int* r) {
    int ll_;
    if (s < 1808) { ll_ = s >> 4; }
    else {
        ll_ = 113;
        for (int c = 113; c < 127; c++) if (span_base(c + 1) <= s) ll_ = c + 1;
    }
    *l = ll_; *r = ll_ + (s - span_base(ll_));
}

// ---------------- input classification (int32 vs int64 vs float) ----------------
__device__ __forceinline__ int classify(const unsigned* p) {
    bool allSmall = true, oddZero = true, anyNZ = false;
    for (int i = 0; i < 64; i++) {
        unsigned v = p[i];
        if (v >= 128u) allSmall = false;
        if ((i & 1) && v != 0u) oddZero = false;
        if (!(i & 1) && v != 0u) anyNZ = true;
    }
    if (!allSmall) return 0;
    return (oddZero && anyNZ) ? 2 : 1;
}

// ---------------- K0: spans + G=exp(-dist) + A bitmask, fused ----------------
#define EXP_BLOCKS ((BATCH * LL * LL) / 256)   // 512
__global__ void k_pre(const float* __restrict__ dist) {
    int bx = blockIdx.x;
    if (bx < EXP_BLOCKS) {
        int i = bx * 256 + threadIdx.x;
        float d = dist[i];
        g_G[i] = expf(-d);
        unsigned m = __ballot_sync(0xffffffffu, d <= 2.0f);
        if ((threadIdx.x & 31) == 0) g_A[i >> 5] = m;
    } else {
        int s = (bx - EXP_BLOCKS) * 256 + threadIdx.x;
        if (s < NSPAN) {
            int l, r; span_lr(s, &l, &r);
            g_lr[s] = (unsigned)l | ((unsigned)r << 8);
        }
    }
}

__device__ __forceinline__ long long read_idx(const void* p, int wide, int off) {
    return wide ? ((const long long*)p)[off] : (long long)((const int*)p)[off];
}

// ---------------- K1: token compaction -> packed uint4 ----------------
__global__ void k_tok(const void* __restrict__ inA, const void* __restrict__ inB) {
    __shared__ int s_swap, s_wide;
    if (threadIdx.x == 0) {
        int cA = classify((const unsigned*)inA), cB = classify((const unsigned*)inB);
        if      (cA > 0) { s_swap = 0; s_wide = (cA == 2); }
        else if (cB > 0) { s_swap = 1; s_wide = (cB == 2); }
        else             { s_swap = 0; s_wide = 0; }
    }
    __syncthreads();
    int gid = blockIdx.x * blockDim.x + threadIdx.x;
    if (gid >= BATCH * NSPAN) return;
    const void*  pIdx = s_swap ? inB : inA;
    const float* hw   = (const float*)(s_swap ? inA : inB);
    int wide = s_wide;

    int b = gid / NSPAN, s = gid - b * NSPAN;
    unsigned lr = g_lr[s];
    int off = ((b * LL + (int)(lr & 0xFF)) * LL + (int)((lr >> 8) & 0xFF)) * 4;

    int ik[3]; float wk[3]; long long raw0 = -1;
    #pragma unroll
    for (int k = 0; k < 3; k++) {
        long long raw = read_idx(pIdx, wide, off + k);
        if (k == 0) raw0 = raw;
        bool v = (raw >= 0);
        ik[k] = v ? (int)raw : (1000 + k);
        wk[k] = v ? hw[off + k] : 0.0f;
    }
    unsigned top1 = (raw0 >= 0) ? (unsigned)min((int)raw0, LL - 1) : 0xFFu;

    bool a1 = true, a2 = true;
    if (ik[1] == ik[0]) { wk[0] = __fadd_rn(wk[0], wk[1]); a1 = false; }
    if (ik[2] == ik[0]) { wk[0] = __fadd_rn(wk[0], wk[2]); a2 = false; }
    else if (a1 && ik[2] == ik[1]) { wk[1] = __fadd_rn(wk[1], wk[2]); a2 = false; }

    int mi[3] = {255, 255, 255}; float mw[3] = {0.f, 0.f, 0.f}; int cnt = 0;
    if (ik[0] < LL)       { mi[cnt] = ik[0]; mw[cnt] = wk[0]; cnt++; }
    if (a1 && ik[1] < LL) { mi[cnt] = ik[1]; mw[cnt] = wk[1]; cnt++; }
    if (a2 && ik[2] < LL) { mi[cnt] = ik[2]; mw[cnt] = wk[2]; cnt++; }

    if (cnt >= 2 && mi[0] > mi[1]) { int t = mi[0]; mi[0] = mi[1]; mi[1] = t;
                                     float f = mw[0]; mw[0] = mw[1]; mw[1] = f; }
    if (cnt == 3) {
        if (mi[1] > mi[2]) { int t = mi[1]; mi[1] = mi[2]; mi[2] = t;
                             float f = mw[1]; mw[1] = mw[2]; mw[2] = f; }
        if (mi[0] > mi[1]) { int t = mi[0]; mi[0] = mi[1]; mi[1] = t;
                             float f = mw[0]; mw[0] = mw[1]; mw[1] = f; }
    }
    unsigned ptk = top1 | ((unsigned)mi[0] << 8) | ((unsigned)mi[1] << 16)
                 | ((unsigned)mi[2] << 24);
    g_cand[gid] = make_uint4(ptk, __float_as_uint(mw[0]),
                             __float_as_uint(mw[1]), __float_as_uint(mw[2]));
}

// ---------------- K2: CAP folded into top1 byte ----------------
__global__ void k_cap() {
    __shared__ unsigned sp[NSPAN];
    int b = blockIdx.x, l = threadIdx.x;
    for (int i = l; i < NSPAN; i += 128) sp[i] = g_cand[b * NSPAN + i].x;
    __syncthreads();
    int cnt = 0;
    for (int t = 0; t < NSPAN; t++) {
        if ((sp[t] & 0xFFu) == (unsigned)l) {
            cnt++;
            if (cnt > 128) sp[t] |= 0xFFu;
        }
    }
    __syncthreads();
    for (int i = l; i < NSPAN; i += 128) g_cand[b * NSPAN + i].x = sp[i];
}

// ---------------- K3 (captured slot): main gate + masked top-10 ----------------
// u64 key = (f32_bits(gate) << 11) | (2047 - t): gate >= 0 so float bits are
// order-monotonic; ties prefer smaller t; key 0 == empty slot (emit s).
__global__ void __launch_bounds__(WPB * 32, 1)
k_main(float* __restrict__ out) {
    __shared__ uint4    sCand[NSPAN];             // 30848 B
    __shared__ float    sApw[WPB][LL];            //  8192 B
    __shared__ unsigned sU[WPB][8];               //   512 B
    __shared__ unsigned sGeo[WPB][64];            //  4096 B

    int b = blockIdx.y;
    int tid = threadIdx.x, lane = tid & 31, warp = tid >> 5;
    int base = b * NSPAN;

    for (int i = tid; i < NSPAN; i += WPB * 32)
        sCand[i] = g_cand[base + i];
    __syncthreads();

    int s = blockIdx.x * WPB + warp;
    if (s >= NSPAN) return;

    uint4 cs = sCand[s];
    int t0 = (cs.x >>  8) & 0xFF;
    int t1 = (cs.x >> 16) & 0xFF;
    int t2 = (cs.x >> 24) & 0xFF;
    float w0 = __uint_as_float(cs.y);
    float w1 = __uint_as_float(cs.z);
    float w2 = __uint_as_float(cs.w);
    const float*    Gb = g_G + b * LL * LL;
    const unsigned* Ab = g_A + b * LL * 4;

    // U bitmask + A_pw row (identical FFMA chain to the passing R10/R11)
    #pragma unroll
    for (int q = 0; q < 4; q++) {
        int m = q * 32 + lane;
        bool bit = false;
        if (t0 < LL) bit |= (t0 == m) || ((Ab[t0 * 4 + q] >> lane) & 1u);
        if (t1 < LL) bit |= (t1 == m) || ((Ab[t1 * 4 + q] >> lane) & 1u);
        if (t2 < LL) bit |= (t2 == m) || ((Ab[t2 * 4 + q] >> lane) & 1u);
        unsigned bal = __ballot_sync(0xffffffffu, bit);
        if (lane == 0) { sU[warp][q] = bal; sU[warp][q + 4] = 0u; }
        float a = __fmaf_rn(w0, Gb[(t0 & 0x7F) * LL + m], 0.0f);
        a = __fmaf_rn(w1, Gb[(t1 & 0x7F) * LL + m], a);
        a = __fmaf_rn(w2, Gb[(t2 & 0x7F) * LL + m], a);
        sApw[warp][m] = a;
    }
    // per-warp geom bitmask over candidate ids
    sGeo[warp][lane] = 0u; sGeo[warp][32 + lane] = 0u;
    __syncwarp();
    if (lane == 0) {
        unsigned lr_s = g_lr[s];
        int ls = lr_s & 0xFF, rs = (lr_s >> 8) & 0xFF;
        const int dl[8] = {-1,-1,-1, 0, 0, 1, 1, 1};
        const int dr[8] = {-1, 0, 1,-1, 1,-1, 0, 1};
        #pragma unroll
        for (int j = 0; j < 8; j++) {
            int nl = ls + dl[j], nr = rs + dr[j];
            if (nl >= 0 && nr >= nl && nr < LL && (nr - nl) <= 15) {
                int id = span_base(nl) + (nr - nl);
                sGeo[warp][id >> 5] |= (1u << (id & 31));
            }
        }
    }
    __syncwarp();

    unsigned long long kv[KSEL];
    #pragma unroll
    for (int j = 0; j < KSEL; j++) kv[j] = 0ull;
    const float* apw = sApw[warp];

    #pragma unroll 2
    for (int k = 0; k < NWORD; k++) {
        int t = k * 32 + lane;
        int tc = (t < NSPAN) ? t : (NSPAN - 1);
        uint4 cd = sCand[tc];
        unsigned gw = sGeo[warp][k];                 // broadcast, conflict-free
        unsigned byte = cd.x & 0xFFu;
        unsigned w_ = sU[warp][byte >> 5];           // 8 words, 8 banks: multicast
        bool pass = ((((w_ >> (byte & 31)) | (gw >> lane)) & 1u) != 0u)
                    && (t != s) && (t < NSPAN);

        float g = __fmaf_rn(__uint_as_float(cd.y), apw[(cd.x >>  8) & 0x7F], 0.0f);
        g = __fmaf_rn(__uint_as_float(cd.z), apw[(cd.x >> 16) & 0x7F], g);
        g = __fmaf_rn(__uint_as_float(cd.w), apw[(cd.x >> 24) & 0x7F], g);

        unsigned long long key = pass
            ? ((((unsigned long long)__float_as_uint(g)) << 11)
               | (unsigned long long)(2047 - t))
            : 0ull;

        if (key > kv[KSEL - 1]) {
            kv[KSEL - 1] = key;
            #pragma unroll
            for (int j = KSEL - 2; j >= 0; j--) {
                if (kv[j + 1] > kv[j]) {
                    unsigned long long tk = kv[j]; kv[j] = kv[j + 1]; kv[j + 1] = tk;
                }
            }
        }
    }

    // butterfly merge: snapshot partner's sorted list, early-break insert
    #pragma unroll
    for (int off = 16; off >= 1; off >>= 1) {
        unsigned long long pk[KSEL];
        #pragma unroll
        for (int j = 0; j < KSEL; j++)
            pk[j] = __shfl_xor_sync(0xffffffffu, kv[j], off);
        #pragma unroll
        for (int j = 0; j < KSEL; j++) {
            if (pk[j] > kv[KSEL - 1]) {
                kv[KSEL - 1] = pk[j];
                #pragma unroll
                for (int k2 = KSEL - 2; k2 >= 0; k2--) {
                    if (kv[k2 + 1] > kv[k2]) {
                        unsigned long long tk = kv[k2];
                        kv[k2] = kv[k2 + 1]; kv[k2 + 1] = tk;
                    }
                }
            } else break;   // pk sorted desc: nothing later can qualify
        }
    }

    if (lane == 0) {
        int ob = (base + s) * KSEL;
        #pragma unroll
        for (int j = 0; j < KSEL; j++) {
            unsigned long long key = kv[j];
            int t = key ? (2047 - (int)(key & 2047ull)) : s;
            out[ob + j] = (float)t;
        }
    }
}

// ---------------- K4: mask-tail fill only ----------------
__global__ void k_tail(float* __restrict__ out, int out_size) {
    int i = BSK + blockIdx.x * blockDim.x + threadIdx.x;
    if (i < out_size) out[i] = 1.0f;
}

// ---------------- launch ----------------
extern "C" void kernel_launch(void* const* d_in, const int* in_sizes, int n_in,
                              void* d_out, int out_size) {
    const void* pA = d_in[0];
    const void* pB = d_in[1];
    const float* dist = (const float*)d_in[2];
    if (in_sizes[0] == BATCH * LL * LL)      { dist = (const float*)d_in[0]; pA = d_in[1]; pB = d_in[2]; }
    else if (in_sizes[1] == BATCH * LL * LL) { dist = (const float*)d_in[1]; pA = d_in[0]; pB = d_in[2]; }
    float* out = (float*)d_out;

    k_pre<<<EXP_BLOCKS + (NSPAN + 255) / 256, 256>>>(dist);          // idx 0
    k_tok<<<(BATCH * NSPAN + 255) / 256, 256>>>(pA, pB);             // idx 1
    k_cap<<<BATCH, 128>>>();                                          // idx 2
    dim3 grid((NSPAN + WPB - 1) / WPB, BATCH);
    k_main<<<grid, WPB * 32>>>(out);                                  // idx 3 (captured)
    int tail = out_size - BSK;
    if (tail > 0) k_tail<<<(tail + 255) / 256, 256>>>(out, out_size); // idx 4
}